// round 3
// baseline (speedup 1.0000x reference)
#include <cuda_runtime.h>
#include <math.h>

#define BB 8
#define SS 2048
#define KIN 128
#define NIN 256
#define NPROC 1024
#define KPROC 256
#define DM 1024

// ---------------- scratch (device globals; no allocation allowed) ----------------
__device__ float g_PWT[NIN * NPROC];          // process_weights^T  [256][1024]
__device__ float g_Wg[BB * KIN * NPROC];      // gathered weights   [8][128][1024]
__device__ float g_part[BB * 16 * NPROC];     // partial col sums   [8][16 mtiles][1024]
__device__ int   g_pidx[BB * KPROC];          // selected neurons   [8][256]
__device__ float g_Wsel[BB * KIN * KPROC];    // selected weights   [8][128][256]
__device__ float g_asel[BB * SS * KPROC];     // selected acts      [8][2048][256]

__device__ __forceinline__ float gelu_exact(float x) {
    return 0.5f * x * (1.0f + erff(x * 0.70710678118654752f));
}

// ---------------- K0: transpose process_weights [1024][256] -> PWT [256][1024] ----
__global__ void k_transpose(const float* __restrict__ pw) {
    __shared__ float t[32][33];
    int x = blockIdx.x * 32 + threadIdx.x;   // col in PW (0..255)
    int y = blockIdx.y * 32 + threadIdx.y;   // row in PW (0..1023)
    #pragma unroll
    for (int i = 0; i < 32; i += 8)
        t[threadIdx.y + i][threadIdx.x] = pw[(y + i) * NIN + x];
    __syncthreads();
    int x2 = blockIdx.y * 32 + threadIdx.x;  // col in PWT (= PW row)
    int y2 = blockIdx.x * 32 + threadIdx.y;  // row in PWT (= PW col)
    #pragma unroll
    for (int i = 0; i < 32; i += 8)
        g_PWT[(y2 + i) * NPROC + x2] = t[threadIdx.x][threadIdx.y + i];
}

// ---------------- K1: gather Wg[b][k][:] = PWT[input_idx[b][k]][:] -----------------
__global__ void k_gather_wg(const int* __restrict__ iidx) {
    int b = blockIdx.x / KIN;
    int k = blockIdx.x % KIN;
    int c = iidx[b * KIN + k];
    const float4* src = (const float4*)&g_PWT[(size_t)c * NPROC];
    float4* dst = (float4*)&g_Wg[((size_t)b * KIN + k) * NPROC];
    dst[threadIdx.x] = src[threadIdx.x];     // 256 thr * float4 = 1024 floats
}

// ---------------- K2: GEMM1 + gelu + per-tile column sums (deterministic) ----------
// grid (16 mtiles, 8 ntiles, 8 batch), 256 threads, 128x128 tile, 8x8 microtile
// double-buffered smem pipeline, one barrier per K-step
__global__ __launch_bounds__(256, 2) void k_scores(const float* __restrict__ X) {
    __shared__ float As[2][16][128];
    __shared__ float Bs[2][16][128];
    int b = blockIdx.z;
    int m0 = blockIdx.x * 128;
    int n0 = blockIdx.y * 128;
    int tid = threadIdx.x;
    int tx = tid & 15, ty = tid >> 4;
    const float* A = X + (size_t)b * SS * KIN;                  // [2048][128]
    const float* Bm = g_Wg + (size_t)b * KIN * NPROC;           // [128][1024]
    // per-thread fixed load coordinates
    int ar0 = (tid) >> 2,        ac0 = (tid & 3) * 4;
    int ar1 = (tid + 256) >> 2,  ac1 = ((tid + 256) & 3) * 4;
    int br0 = tid >> 5,          bc0 = (tid & 31) * 4;
    int br1 = (tid + 256) >> 5,  bc1 = ((tid + 256) & 31) * 4;

    float acc[8][8];
    #pragma unroll
    for (int i = 0; i < 8; i++)
        #pragma unroll
        for (int j = 0; j < 8; j++) acc[i][j] = 0.f;

    // prologue: tile 0
    {
        float4 a0 = *(const float4*)&A[(m0 + ar0) * KIN + ac0];
        float4 a1 = *(const float4*)&A[(m0 + ar1) * KIN + ac1];
        As[0][ac0 + 0][ar0] = a0.x; As[0][ac0 + 1][ar0] = a0.y;
        As[0][ac0 + 2][ar0] = a0.z; As[0][ac0 + 3][ar0] = a0.w;
        As[0][ac1 + 0][ar1] = a1.x; As[0][ac1 + 1][ar1] = a1.y;
        As[0][ac1 + 2][ar1] = a1.z; As[0][ac1 + 3][ar1] = a1.w;
        *(float4*)&Bs[0][br0][bc0] = *(const float4*)&Bm[br0 * NPROC + n0 + bc0];
        *(float4*)&Bs[0][br1][bc1] = *(const float4*)&Bm[br1 * NPROC + n0 + bc1];
    }
    __syncthreads();

    const int NT = KIN / 16;  // 8
    #pragma unroll
    for (int t = 0; t < NT; t++) {
        int cur = t & 1;
        float4 pa0, pa1, pb0, pb1;
        if (t + 1 < NT) {
            int kc = (t + 1) * 16;
            pa0 = *(const float4*)&A[(m0 + ar0) * KIN + kc + ac0];
            pa1 = *(const float4*)&A[(m0 + ar1) * KIN + kc + ac1];
            pb0 = *(const float4*)&Bm[(kc + br0) * NPROC + n0 + bc0];
            pb1 = *(const float4*)&Bm[(kc + br1) * NPROC + n0 + bc1];
        }
        #pragma unroll
        for (int kk = 0; kk < 16; kk++) {
            float a[8], bv[8];
            #pragma unroll
            for (int i = 0; i < 8; i++) a[i] = As[cur][kk][ty * 8 + i];
            #pragma unroll
            for (int j = 0; j < 8; j++) bv[j] = Bs[cur][kk][tx * 8 + j];
            #pragma unroll
            for (int i = 0; i < 8; i++)
                #pragma unroll
                for (int j = 0; j < 8; j++) acc[i][j] += a[i] * bv[j];
        }
        if (t + 1 < NT) {
            int nxt = cur ^ 1;
            As[nxt][ac0 + 0][ar0] = pa0.x; As[nxt][ac0 + 1][ar0] = pa0.y;
            As[nxt][ac0 + 2][ar0] = pa0.z; As[nxt][ac0 + 3][ar0] = pa0.w;
            As[nxt][ac1 + 0][ar1] = pa1.x; As[nxt][ac1 + 1][ar1] = pa1.y;
            As[nxt][ac1 + 2][ar1] = pa1.z; As[nxt][ac1 + 3][ar1] = pa1.w;
            *(float4*)&Bs[nxt][br0][bc0] = pb0;
            *(float4*)&Bs[nxt][br1][bc1] = pb1;
            __syncthreads();
        }
    }
    // gelu + column sums within thread, then reduce across 16 thread-rows via smem
    float cs[8];
    #pragma unroll
    for (int j = 0; j < 8; j++) {
        cs[j] = 0.f;
        #pragma unroll
        for (int i = 0; i < 8; i++) cs[j] += gelu_exact(acc[i][j]);
    }
    __syncthreads();
    #pragma unroll
    for (int j = 0; j < 8; j++) As[0][ty][tx * 8 + j] = cs[j];   // reuse As [16][128]
    __syncthreads();
    if (tid < 128) {
        float s = 0.f;
        #pragma unroll
        for (int r = 0; r < 16; r++) s += As[0][r][tid];
        g_part[((size_t)b * 16 + blockIdx.x) * NPROC + n0 + tid] = s;
    }
}

// ---------------- K4: per-batch reduce + bitonic top-256 of 1024 -------------------
__global__ __launch_bounds__(256) void k_topk() {
    __shared__ float sv[NPROC];
    __shared__ int   si[NPROC];
    int b = blockIdx.x;
    int tid = threadIdx.x;
    // reduce the 16 per-mtile partials in fixed order (deterministic)
    for (int t = tid; t < NPROC; t += 256) {
        float s = 0.f;
        #pragma unroll
        for (int r = 0; r < 16; r++) s += g_part[((size_t)b * 16 + r) * NPROC + t];
        sv[t] = s; si[t] = t;
    }
    __syncthreads();
    for (int k = 2; k <= NPROC; k <<= 1) {
        for (int j = k >> 1; j > 0; j >>= 1) {
            #pragma unroll 2
            for (int t = tid; t < NPROC; t += 256) {
                int ixj = t ^ j;
                if (ixj > t) {
                    bool desc = ((t & k) == 0);
                    float v1 = sv[t], v2 = sv[ixj];
                    if ((v1 < v2) == desc) {
                        sv[t] = v2; sv[ixj] = v1;
                        int tmp = si[t]; si[t] = si[ixj]; si[ixj] = tmp;
                    }
                }
            }
            __syncthreads();
        }
    }
    if (tid < KPROC) g_pidx[b * KPROC + tid] = si[tid];
}

// ---------------- K4b: Wsel gather — massively parallel ----------------------------
// grid (KIN, BB), 256 threads: Wsel[b][k][j] = Wg[b][k][pidx[b][j]]
__global__ void k_gather_wsel() {
    int b = blockIdx.y, k = blockIdx.x, j = threadIdx.x;
    int col = g_pidx[b * KPROC + j];
    g_Wsel[((size_t)b * KIN + k) * KPROC + j] =
        g_Wg[((size_t)b * KIN + k) * NPROC + col];
}

// ---------------- K5: acts_sel = gelu(X @ Wsel)  [2048,128]x[128,256] --------------
// grid (16, 2, 8), double-buffered
__global__ __launch_bounds__(256, 2) void k_actsel(const float* __restrict__ X) {
    __shared__ float As[2][16][128];
    __shared__ float Bs[2][16][128];
    int b = blockIdx.z;
    int m0 = blockIdx.x * 128;
    int n0 = blockIdx.y * 128;
    int tid = threadIdx.x;
    int tx = tid & 15, ty = tid >> 4;
    const float* A = X + (size_t)b * SS * KIN;
    const float* Bm = g_Wsel + (size_t)b * KIN * KPROC;         // [128][256]
    int ar0 = (tid) >> 2,        ac0 = (tid & 3) * 4;
    int ar1 = (tid + 256) >> 2,  ac1 = ((tid + 256) & 3) * 4;
    int br0 = tid >> 5,          bc0 = (tid & 31) * 4;
    int br1 = (tid + 256) >> 5,  bc1 = ((tid + 256) & 31) * 4;

    float acc[8][8];
    #pragma unroll
    for (int i = 0; i < 8; i++)
        #pragma unroll
        for (int j = 0; j < 8; j++) acc[i][j] = 0.f;

    {
        float4 a0 = *(const float4*)&A[(m0 + ar0) * KIN + ac0];
        float4 a1 = *(const float4*)&A[(m0 + ar1) * KIN + ac1];
        As[0][ac0 + 0][ar0] = a0.x; As[0][ac0 + 1][ar0] = a0.y;
        As[0][ac0 + 2][ar0] = a0.z; As[0][ac0 + 3][ar0] = a0.w;
        As[0][ac1 + 0][ar1] = a1.x; As[0][ac1 + 1][ar1] = a1.y;
        As[0][ac1 + 2][ar1] = a1.z; As[0][ac1 + 3][ar1] = a1.w;
        *(float4*)&Bs[0][br0][bc0] = *(const float4*)&Bm[br0 * KPROC + n0 + bc0];
        *(float4*)&Bs[0][br1][bc1] = *(const float4*)&Bm[br1 * KPROC + n0 + bc1];
    }
    __syncthreads();

    const int NT = KIN / 16;  // 8
    #pragma unroll
    for (int t = 0; t < NT; t++) {
        int cur = t & 1;
        float4 pa0, pa1, pb0, pb1;
        if (t + 1 < NT) {
            int kc = (t + 1) * 16;
            pa0 = *(const float4*)&A[(m0 + ar0) * KIN + kc + ac0];
            pa1 = *(const float4*)&A[(m0 + ar1) * KIN + kc + ac1];
            pb0 = *(const float4*)&Bm[(kc + br0) * KPROC + n0 + bc0];
            pb1 = *(const float4*)&Bm[(kc + br1) * KPROC + n0 + bc1];
        }
        #pragma unroll
        for (int kk = 0; kk < 16; kk++) {
            float a[8], bv[8];
            #pragma unroll
            for (int i = 0; i < 8; i++) a[i] = As[cur][kk][ty * 8 + i];
            #pragma unroll
            for (int j = 0; j < 8; j++) bv[j] = Bs[cur][kk][tx * 8 + j];
            #pragma unroll
            for (int i = 0; i < 8; i++)
                #pragma unroll
                for (int j = 0; j < 8; j++) acc[i][j] += a[i] * bv[j];
        }
        if (t + 1 < NT) {
            int nxt = cur ^ 1;
            As[nxt][ac0 + 0][ar0] = pa0.x; As[nxt][ac0 + 1][ar0] = pa0.y;
            As[nxt][ac0 + 2][ar0] = pa0.z; As[nxt][ac0 + 3][ar0] = pa0.w;
            As[nxt][ac1 + 0][ar1] = pa1.x; As[nxt][ac1 + 1][ar1] = pa1.y;
            As[nxt][ac1 + 2][ar1] = pa1.z; As[nxt][ac1 + 3][ar1] = pa1.w;
            *(float4*)&Bs[nxt][br0][bc0] = pb0;
            *(float4*)&Bs[nxt][br1][bc1] = pb1;
            __syncthreads();
        }
    }
    #pragma unroll
    for (int i = 0; i < 8; i++) {
        int m = m0 + ty * 8 + i;
        float4 v0 = make_float4(gelu_exact(acc[i][0]), gelu_exact(acc[i][1]),
                                gelu_exact(acc[i][2]), gelu_exact(acc[i][3]));
        float4 v1 = make_float4(gelu_exact(acc[i][4]), gelu_exact(acc[i][5]),
                                gelu_exact(acc[i][6]), gelu_exact(acc[i][7]));
        float* dst = &g_asel[((size_t)b * SS + m) * KPROC + n0 + tx * 8];
        *(float4*)dst = v0;
        *(float4*)(dst + 4) = v1;
    }
}

// ---------------- K6: out = acts_sel @ gather(P)  [2048,256]x[256,1024] ------------
// grid (16, 8, 8), double-buffered
__global__ __launch_bounds__(256, 2) void k_out(const float* __restrict__ P,
                                                float* __restrict__ out) {
    __shared__ float As[2][16][128];
    __shared__ float Bs[2][16][128];
    int b = blockIdx.z;
    int m0 = blockIdx.x * 128;
    int n0 = blockIdx.y * 128;
    int tid = threadIdx.x;
    int tx = tid & 15, ty = tid >> 4;
    const float* A = g_asel + (size_t)b * SS * KPROC;           // [2048][256]
    const int* pidx = g_pidx + b * KPROC;
    int ar0 = (tid) >> 2,        ac0 = (tid & 3) * 4;
    int ar1 = (tid + 256) >> 2,  ac1 = ((tid + 256) & 3) * 4;
    int br0 = tid >> 5,          bc0 = (tid & 31) * 4;
    int br1 = (tid + 256) >> 5,  bc1 = ((tid + 256) & 31) * 4;

    float acc[8][8];
    #pragma unroll
    for (int i = 0; i < 8; i++)
        #pragma unroll
        for (int j = 0; j < 8; j++) acc[i][j] = 0.f;

    {
        float4 a0 = *(const float4*)&A[(m0 + ar0) * KPROC + ac0];
        float4 a1 = *(const float4*)&A[(m0 + ar1) * KPROC + ac1];
        As[0][ac0 + 0][ar0] = a0.x; As[0][ac0 + 1][ar0] = a0.y;
        As[0][ac0 + 2][ar0] = a0.z; As[0][ac0 + 3][ar0] = a0.w;
        As[0][ac1 + 0][ar1] = a1.x; As[0][ac1 + 1][ar1] = a1.y;
        As[0][ac1 + 2][ar1] = a1.z; As[0][ac1 + 3][ar1] = a1.w;
        int p0 = pidx[br0], p1 = pidx[br1];
        *(float4*)&Bs[0][br0][bc0] = *(const float4*)&P[(size_t)p0 * DM + n0 + bc0];
        *(float4*)&Bs[0][br1][bc1] = *(const float4*)&P[(size_t)p1 * DM + n0 + bc1];
    }
    __syncthreads();

    const int NT = KPROC / 16;  // 16
    #pragma unroll 4
    for (int t = 0; t < NT; t++) {
        int cur = t & 1;
        float4 pa0, pa1, pb0, pb1;
        if (t + 1 < NT) {
            int kc = (t + 1) * 16;
            pa0 = *(const float4*)&A[(m0 + ar0) * KPROC + kc + ac0];
            pa1 = *(const float4*)&A[(m0 + ar1) * KPROC + kc + ac1];
            int p0 = pidx[kc + br0], p1 = pidx[kc + br1];
            pb0 = *(const float4*)&P[(size_t)p0 * DM + n0 + bc0];
            pb1 = *(const float4*)&P[(size_t)p1 * DM + n0 + bc1];
        }
        #pragma unroll
        for (int kk = 0; kk < 16; kk++) {
            float a[8], bv[8];
            #pragma unroll
            for (int i = 0; i < 8; i++) a[i] = As[cur][kk][ty * 8 + i];
            #pragma unroll
            for (int j = 0; j < 8; j++) bv[j] = Bs[cur][kk][tx * 8 + j];
            #pragma unroll
            for (int i = 0; i < 8; i++)
                #pragma unroll
                for (int j = 0; j < 8; j++) acc[i][j] += a[i] * bv[j];
        }
        if (t + 1 < NT) {
            int nxt = cur ^ 1;
            As[nxt][ac0 + 0][ar0] = pa0.x; As[nxt][ac0 + 1][ar0] = pa0.y;
            As[nxt][ac0 + 2][ar0] = pa0.z; As[nxt][ac0 + 3][ar0] = pa0.w;
            As[nxt][ac1 + 0][ar1] = pa1.x; As[nxt][ac1 + 1][ar1] = pa1.y;
            As[nxt][ac1 + 2][ar1] = pa1.z; As[nxt][ac1 + 3][ar1] = pa1.w;
            *(float4*)&Bs[nxt][br0][bc0] = pb0;
            *(float4*)&Bs[nxt][br1][bc1] = pb1;
            __syncthreads();
        }
    }
    #pragma unroll
    for (int i = 0; i < 8; i++) {
        int m = m0 + ty * 8 + i;
        float* dst = &out[((size_t)b * SS + m) * DM + n0 + tx * 8];
        *(float4*)dst = make_float4(acc[i][0], acc[i][1], acc[i][2], acc[i][3]);
        *(float4*)(dst + 4) = make_float4(acc[i][4], acc[i][5], acc[i][6], acc[i][7]);
    }
}

// ---------------- launch -----------------------------------------------------------
extern "C" void kernel_launch(void* const* d_in, const int* in_sizes, int n_in,
                              void* d_out, int out_size) {
    const float* X    = (const float*)d_in[0];   // [8,2048,128]
    const float* PW   = (const float*)d_in[1];   // [1024,256]
    const float* PO   = (const float*)d_in[2];   // [1024,1024]
    const int*   IIDX = (const int*)d_in[3];     // [8,128]

    k_transpose<<<dim3(NIN / 32, NPROC / 32), dim3(32, 8)>>>(PW);
    k_gather_wg<<<BB * KIN, 256>>>(IIDX);
    k_scores<<<dim3(16, 8, BB), 256>>>(X);
    k_topk<<<BB, 256>>>();
    k_gather_wsel<<<dim3(KIN, BB), 256>>>();
    k_actsel<<<dim3(16, 2, BB), 256>>>(X);
    k_out<<<dim3(16, 8, BB), 256>>>(PO, (float*)d_out);
}

// round 4
// speedup vs baseline: 1.1720x; 1.1720x over previous
#include <cuda_runtime.h>
#include <math.h>

#define BB 8
#define SS 2048
#define KIN 128
#define NIN 256
#define NPROC 1024
#define KPROC 256
#define DM 1024

// ---------------- scratch (device globals; no allocation allowed) ----------------
__device__ float g_PWT[NIN * NPROC];          // process_weights^T  [256][1024]
__device__ float g_Wg[BB * KIN * NPROC];      // gathered weights   [8][128][1024]
__device__ float g_part[BB * 16 * NPROC];     // partial col sums   [8][16 mtiles][1024]
__device__ int   g_pidx[BB * KPROC];          // selected neurons   [8][256]
__device__ float g_Wsel[BB * KIN * KPROC];    // selected weights   [8][128][256]
__device__ float g_asel[BB * SS * KPROC];     // selected acts      [8][2048][256]

__device__ __forceinline__ float gelu_exact(float x) {
    return 0.5f * x * (1.0f + erff(x * 0.70710678118654752f));
}

// ---------------- K0: transpose process_weights [1024][256] -> PWT [256][1024] ----
__global__ void k_transpose(const float* __restrict__ pw) {
    __shared__ float t[32][33];
    int x = blockIdx.x * 32 + threadIdx.x;   // col in PW (0..255)
    int y = blockIdx.y * 32 + threadIdx.y;   // row in PW (0..1023)
    #pragma unroll
    for (int i = 0; i < 32; i += 8)
        t[threadIdx.y + i][threadIdx.x] = pw[(y + i) * NIN + x];
    __syncthreads();
    int x2 = blockIdx.y * 32 + threadIdx.x;  // col in PWT (= PW row)
    int y2 = blockIdx.x * 32 + threadIdx.y;  // row in PWT (= PW col)
    #pragma unroll
    for (int i = 0; i < 32; i += 8)
        g_PWT[(y2 + i) * NPROC + x2] = t[threadIdx.x][threadIdx.y + i];
}

// ---------------- K1: gather Wg[b][k][:] = PWT[input_idx[b][k]][:] -----------------
__global__ void k_gather_wg(const int* __restrict__ iidx) {
    int b = blockIdx.x / KIN;
    int k = blockIdx.x % KIN;
    int c = iidx[b * KIN + k];
    const float4* src = (const float4*)&g_PWT[(size_t)c * NPROC];
    float4* dst = (float4*)&g_Wg[((size_t)b * KIN + k) * NPROC];
    dst[threadIdx.x] = src[threadIdx.x];     // 256 thr * float4 = 1024 floats
}

// ---------------- K2: GEMM1 + gelu + per-tile column sums (deterministic) ----------
// grid (16 mtiles, 8 ntiles, 8 batch), 256 threads, 128x128 tile, 8x8 microtile
// (single-buffer R2 body — double-buffer regressed via register pressure)
__global__ __launch_bounds__(256) void k_scores(const float* __restrict__ X) {
    __shared__ float As[16][128];
    __shared__ float Bs[16][128];
    int b = blockIdx.z;
    int m0 = blockIdx.x * 128;
    int n0 = blockIdx.y * 128;
    int tid = threadIdx.x;
    int tx = tid & 15, ty = tid >> 4;
    const float* A = X + (size_t)b * SS * KIN;                  // [2048][128]
    const float* Bm = g_Wg + (size_t)b * KIN * NPROC;           // [128][1024]
    float acc[8][8];
    #pragma unroll
    for (int i = 0; i < 8; i++)
        #pragma unroll
        for (int j = 0; j < 8; j++) acc[i][j] = 0.f;

    for (int kc = 0; kc < KIN; kc += 16) {
        #pragma unroll
        for (int it = 0; it < 2; it++) {      // A tile [128m][16k] -> As[k][m]
            int idx = tid + it * 256;
            int row = idx >> 2, c4 = idx & 3;
            float4 v = *(const float4*)&A[(m0 + row) * KIN + kc + c4 * 4];
            As[c4 * 4 + 0][row] = v.x; As[c4 * 4 + 1][row] = v.y;
            As[c4 * 4 + 2][row] = v.z; As[c4 * 4 + 3][row] = v.w;
        }
        #pragma unroll
        for (int it = 0; it < 2; it++) {      // B tile [16k][128n]
            int idx = tid + it * 256;
            int row = idx >> 5, c4 = idx & 31;
            *(float4*)&Bs[row][c4 * 4] =
                *(const float4*)&Bm[(kc + row) * NPROC + n0 + c4 * 4];
        }
        __syncthreads();
        #pragma unroll
        for (int kk = 0; kk < 16; kk++) {
            float a[8], bv[8];
            #pragma unroll
            for (int i = 0; i < 8; i++) a[i] = As[kk][ty * 8 + i];
            #pragma unroll
            for (int j = 0; j < 8; j++) bv[j] = Bs[kk][tx * 8 + j];
            #pragma unroll
            for (int i = 0; i < 8; i++)
                #pragma unroll
                for (int j = 0; j < 8; j++) acc[i][j] += a[i] * bv[j];
        }
        __syncthreads();
    }
    // gelu + column sums within thread, then reduce across 16 thread-rows via smem
    float cs[8];
    #pragma unroll
    for (int j = 0; j < 8; j++) {
        cs[j] = 0.f;
        #pragma unroll
        for (int i = 0; i < 8; i++) cs[j] += gelu_exact(acc[i][j]);
    }
    #pragma unroll
    for (int j = 0; j < 8; j++) As[ty][tx * 8 + j] = cs[j];   // reuse As [16][128]
    __syncthreads();
    if (tid < 128) {
        float s = 0.f;
        #pragma unroll
        for (int r = 0; r < 16; r++) s += As[r][tid];
        g_part[((size_t)b * 16 + blockIdx.x) * NPROC + n0 + tid] = s;
    }
}

// ---------------- K4: per-batch reduce + bitonic top-256 of 1024 -------------------
// 512 threads: one comparator per thread per phase (same network -> same result)
__global__ __launch_bounds__(512) void k_topk() {
    __shared__ float sv[NPROC];
    __shared__ int   si[NPROC];
    int b = blockIdx.x;
    int tid = threadIdx.x;
    // reduce the 16 per-mtile partials in fixed order (deterministic)
    for (int t = tid; t < NPROC; t += 512) {
        float s = 0.f;
        #pragma unroll
        for (int r = 0; r < 16; r++) s += g_part[((size_t)b * 16 + r) * NPROC + t];
        sv[t] = s; si[t] = t;
    }
    __syncthreads();
    for (int k = 2; k <= NPROC; k <<= 1) {
        for (int j = k >> 1; j > 0; j >>= 1) {
            int i = ((tid & ~(j - 1)) << 1) | (tid & (j - 1));
            int ixj = i | j;
            bool desc = ((i & k) == 0);
            float v1 = sv[i], v2 = sv[ixj];
            if ((v1 < v2) == desc) {
                sv[i] = v2; sv[ixj] = v1;
                int tmp = si[i]; si[i] = si[ixj]; si[ixj] = tmp;
            }
            __syncthreads();
        }
    }
    if (tid < KPROC) g_pidx[b * KPROC + tid] = si[tid];
}

// ---------------- K4b: Wsel gather — massively parallel ----------------------------
// grid (KIN, BB), 256 threads: Wsel[b][k][j] = Wg[b][k][pidx[b][j]]
__global__ void k_gather_wsel() {
    int b = blockIdx.y, k = blockIdx.x, j = threadIdx.x;
    int col = g_pidx[b * KPROC + j];
    g_Wsel[((size_t)b * KIN + k) * KPROC + j] =
        g_Wg[((size_t)b * KIN + k) * NPROC + col];
}

// ---------------- K5: acts_sel = gelu(X @ Wsel)  [2048,128]x[128,256] --------------
// grid (16, 2, 8), single-buffer
__global__ __launch_bounds__(256) void k_actsel(const float* __restrict__ X) {
    __shared__ float As[16][128];
    __shared__ float Bs[16][128];
    int b = blockIdx.z;
    int m0 = blockIdx.x * 128;
    int n0 = blockIdx.y * 128;
    int tid = threadIdx.x;
    int tx = tid & 15, ty = tid >> 4;
    const float* A = X + (size_t)b * SS * KIN;
    const float* Bm = g_Wsel + (size_t)b * KIN * KPROC;         // [128][256]
    float acc[8][8];
    #pragma unroll
    for (int i = 0; i < 8; i++)
        #pragma unroll
        for (int j = 0; j < 8; j++) acc[i][j] = 0.f;

    for (int kc = 0; kc < KIN; kc += 16) {
        #pragma unroll
        for (int it = 0; it < 2; it++) {
            int idx = tid + it * 256;
            int row = idx >> 2, c4 = idx & 3;
            float4 v = *(const float4*)&A[(m0 + row) * KIN + kc + c4 * 4];
            As[c4 * 4 + 0][row] = v.x; As[c4 * 4 + 1][row] = v.y;
            As[c4 * 4 + 2][row] = v.z; As[c4 * 4 + 3][row] = v.w;
        }
        #pragma unroll
        for (int it = 0; it < 2; it++) {
            int idx = tid + it * 256;
            int row = idx >> 5, c4 = idx & 31;
            *(float4*)&Bs[row][c4 * 4] =
                *(const float4*)&Bm[(kc + row) * KPROC + n0 + c4 * 4];
        }
        __syncthreads();
        #pragma unroll
        for (int kk = 0; kk < 16; kk++) {
            float a[8], bv[8];
            #pragma unroll
            for (int i = 0; i < 8; i++) a[i] = As[kk][ty * 8 + i];
            #pragma unroll
            for (int j = 0; j < 8; j++) bv[j] = Bs[kk][tx * 8 + j];
            #pragma unroll
            for (int i = 0; i < 8; i++)
                #pragma unroll
                for (int j = 0; j < 8; j++) acc[i][j] += a[i] * bv[j];
        }
        __syncthreads();
    }
    #pragma unroll
    for (int i = 0; i < 8; i++) {
        int m = m0 + ty * 8 + i;
        float4 v0 = make_float4(gelu_exact(acc[i][0]), gelu_exact(acc[i][1]),
                                gelu_exact(acc[i][2]), gelu_exact(acc[i][3]));
        float4 v1 = make_float4(gelu_exact(acc[i][4]), gelu_exact(acc[i][5]),
                                gelu_exact(acc[i][6]), gelu_exact(acc[i][7]));
        float* dst = &g_asel[((size_t)b * SS + m) * KPROC + n0 + tx * 8];
        *(float4*)dst = v0;
        *(float4*)(dst + 4) = v1;
    }
}

// ---------------- K6: out = acts_sel @ gather(P)  [2048,256]x[256,1024] ------------
// grid (16, 8, 8), single-buffer
__global__ __launch_bounds__(256) void k_out(const float* __restrict__ P,
                                             float* __restrict__ out) {
    __shared__ float As[16][128];
    __shared__ float Bs[16][128];
    int b = blockIdx.z;
    int m0 = blockIdx.x * 128;
    int n0 = blockIdx.y * 128;
    int tid = threadIdx.x;
    int tx = tid & 15, ty = tid >> 4;
    const float* A = g_asel + (size_t)b * SS * KPROC;           // [2048][256]
    const int* pidx = g_pidx + b * KPROC;
    float acc[8][8];
    #pragma unroll
    for (int i = 0; i < 8; i++)
        #pragma unroll
        for (int j = 0; j < 8; j++) acc[i][j] = 0.f;

    for (int kc = 0; kc < KPROC; kc += 16) {
        #pragma unroll
        for (int it = 0; it < 2; it++) {      // A tile [128m][16k] -> As[k][m]
            int idx = tid + it * 256;
            int row = idx >> 2, c4 = idx & 3;
            float4 v = *(const float4*)&A[(m0 + row) * KPROC + kc + c4 * 4];
            As[c4 * 4 + 0][row] = v.x; As[c4 * 4 + 1][row] = v.y;
            As[c4 * 4 + 2][row] = v.z; As[c4 * 4 + 3][row] = v.w;
        }
        #pragma unroll
        for (int it = 0; it < 2; it++) {      // B tile: gathered rows of P
            int idx = tid + it * 256;
            int row = idx >> 5, c4 = idx & 31;
            int pr = pidx[kc + row];
            *(float4*)&Bs[row][c4 * 4] =
                *(const float4*)&P[(size_t)pr * DM + n0 + c4 * 4];
        }
        __syncthreads();
        #pragma unroll
        for (int kk = 0; kk < 16; kk++) {
            float a[8], bv[8];
            #pragma unroll
            for (int i = 0; i < 8; i++) a[i] = As[kk][ty * 8 + i];
            #pragma unroll
            for (int j = 0; j < 8; j++) bv[j] = Bs[kk][tx * 8 + j];
            #pragma unroll
            for (int i = 0; i < 8; i++)
                #pragma unroll
                for (int j = 0; j < 8; j++) acc[i][j] += a[i] * bv[j];
        }
        __syncthreads();
    }
    #pragma unroll
    for (int i = 0; i < 8; i++) {
        int m = m0 + ty * 8 + i;
        float* dst = &out[((size_t)b * SS + m) * DM + n0 + tx * 8];
        *(float4*)dst = make_float4(acc[i][0], acc[i][1], acc[i][2], acc[i][3]);
        *(float4*)(dst + 4) = make_float4(acc[i][4], acc[i][5], acc[i][6], acc[i][7]);
    }
}

// ---------------- launch -----------------------------------------------------------
extern "C" void kernel_launch(void* const* d_in, const int* in_sizes, int n_in,
                              void* d_out, int out_size) {
    const float* X    = (const float*)d_in[0];   // [8,2048,128]
    const float* PW   = (const float*)d_in[1];   // [1024,256]
    const float* PO   = (const float*)d_in[2];   // [1024,1024]
    const int*   IIDX = (const int*)d_in[3];     // [8,128]

    k_transpose<<<dim3(NIN / 32, NPROC / 32), dim3(32, 8)>>>(PW);
    k_gather_wg<<<BB * KIN, 256>>>(IIDX);
    k_scores<<<dim3(16, 8, BB), 256>>>(X);
    k_topk<<<BB, 512>>>();
    k_gather_wsel<<<dim3(KIN, BB), 256>>>();
    k_actsel<<<dim3(16, 2, BB), 256>>>(X);
    k_out<<<dim3(16, 8, BB), 256>>>(PO, (float*)d_out);
}

// round 5
// speedup vs baseline: 1.3960x; 1.1912x over previous
#include <cuda_runtime.h>
#include <math.h>
#include <mma.h>

using namespace nvcuda;

#define BB 8
#define SS 2048
#define KIN 128
#define NIN 256
#define NPROC 1024
#define KPROC 256
#define DM 1024

// ---------------- scratch (device globals; no allocation allowed) ----------------
__device__ float g_PWT[NIN * NPROC];          // process_weights^T  [256][1024]
__device__ float g_Wg[BB * KIN * NPROC];      // gathered weights   [8][128][1024]
__device__ float g_part[BB * 16 * NPROC];     // partial col sums   [8][16 mtiles][1024]
__device__ int   g_pidx[BB * KPROC];          // selected neurons   [8][256]
__device__ float g_Wsel[BB * KIN * KPROC];    // selected weights   [8][128][256]
__device__ float g_asel[BB * SS * KPROC];     // selected acts      [8][2048][256]

__device__ __forceinline__ float gelu_exact(float x) {
    return 0.5f * x * (1.0f + erff(x * 0.70710678118654752f));
}

// ---------------- K0: transpose process_weights [1024][256] -> PWT [256][1024] ----
__global__ void k_transpose(const float* __restrict__ pw) {
    __shared__ float t[32][33];
    int x = blockIdx.x * 32 + threadIdx.x;
    int y = blockIdx.y * 32 + threadIdx.y;
    #pragma unroll
    for (int i = 0; i < 32; i += 8)
        t[threadIdx.y + i][threadIdx.x] = pw[(y + i) * NIN + x];
    __syncthreads();
    int x2 = blockIdx.y * 32 + threadIdx.x;
    int y2 = blockIdx.x * 32 + threadIdx.y;
    #pragma unroll
    for (int i = 0; i < 32; i += 8)
        g_PWT[(y2 + i) * NPROC + x2] = t[threadIdx.x][threadIdx.y + i];
}

// ---------------- K1: gather Wg[b][k][:] = PWT[input_idx[b][k]][:] -----------------
__global__ void k_gather_wg(const int* __restrict__ iidx) {
    int b = blockIdx.x / KIN;
    int k = blockIdx.x % KIN;
    int c = iidx[b * KIN + k];
    const float4* src = (const float4*)&g_PWT[(size_t)c * NPROC];
    float4* dst = (float4*)&g_Wg[((size_t)b * KIN + k) * NPROC];
    dst[threadIdx.x] = src[threadIdx.x];
}

// ---------------- K2: GEMM1 + gelu + per-tile column sums (fp32-exact; selection) --
__global__ __launch_bounds__(256) void k_scores(const float* __restrict__ X) {
    __shared__ float As[16][128];
    __shared__ float Bs[16][128];
    int b = blockIdx.z;
    int m0 = blockIdx.x * 128;
    int n0 = blockIdx.y * 128;
    int tid = threadIdx.x;
    int tx = tid & 15, ty = tid >> 4;
    const float* A = X + (size_t)b * SS * KIN;
    const float* Bm = g_Wg + (size_t)b * KIN * NPROC;
    float acc[8][8];
    #pragma unroll
    for (int i = 0; i < 8; i++)
        #pragma unroll
        for (int j = 0; j < 8; j++) acc[i][j] = 0.f;

    for (int kc = 0; kc < KIN; kc += 16) {
        #pragma unroll
        for (int it = 0; it < 2; it++) {
            int idx = tid + it * 256;
            int row = idx >> 2, c4 = idx & 3;
            float4 v = *(const float4*)&A[(m0 + row) * KIN + kc + c4 * 4];
            As[c4 * 4 + 0][row] = v.x; As[c4 * 4 + 1][row] = v.y;
            As[c4 * 4 + 2][row] = v.z; As[c4 * 4 + 3][row] = v.w;
        }
        #pragma unroll
        for (int it = 0; it < 2; it++) {
            int idx = tid + it * 256;
            int row = idx >> 5, c4 = idx & 31;
            *(float4*)&Bs[row][c4 * 4] =
                *(const float4*)&Bm[(kc + row) * NPROC + n0 + c4 * 4];
        }
        __syncthreads();
        #pragma unroll
        for (int kk = 0; kk < 16; kk++) {
            float a[8], bv[8];
            #pragma unroll
            for (int i = 0; i < 8; i++) a[i] = As[kk][ty * 8 + i];
            #pragma unroll
            for (int j = 0; j < 8; j++) bv[j] = Bs[kk][tx * 8 + j];
            #pragma unroll
            for (int i = 0; i < 8; i++)
                #pragma unroll
                for (int j = 0; j < 8; j++) acc[i][j] += a[i] * bv[j];
        }
        __syncthreads();
    }
    float cs[8];
    #pragma unroll
    for (int j = 0; j < 8; j++) {
        cs[j] = 0.f;
        #pragma unroll
        for (int i = 0; i < 8; i++) cs[j] += gelu_exact(acc[i][j]);
    }
    #pragma unroll
    for (int j = 0; j < 8; j++) As[ty][tx * 8 + j] = cs[j];
    __syncthreads();
    if (tid < 128) {
        float s = 0.f;
        #pragma unroll
        for (int r = 0; r < 16; r++) s += As[r][tid];
        g_part[((size_t)b * 16 + blockIdx.x) * NPROC + n0 + tid] = s;
    }
}

// ---------------- K4: per-batch reduce + bitonic top-256 of 1024 -------------------
__global__ __launch_bounds__(512) void k_topk() {
    __shared__ float sv[NPROC];
    __shared__ int   si[NPROC];
    int b = blockIdx.x;
    int tid = threadIdx.x;
    for (int t = tid; t < NPROC; t += 512) {
        float s = 0.f;
        #pragma unroll
        for (int r = 0; r < 16; r++) s += g_part[((size_t)b * 16 + r) * NPROC + t];
        sv[t] = s; si[t] = t;
    }
    __syncthreads();
    for (int k = 2; k <= NPROC; k <<= 1) {
        for (int j = k >> 1; j > 0; j >>= 1) {
            int i = ((tid & ~(j - 1)) << 1) | (tid & (j - 1));
            int ixj = i | j;
            bool desc = ((i & k) == 0);
            float v1 = sv[i], v2 = sv[ixj];
            if ((v1 < v2) == desc) {
                sv[i] = v2; sv[ixj] = v1;
                int tmp = si[i]; si[i] = si[ixj]; si[ixj] = tmp;
            }
            __syncthreads();
        }
    }
    if (tid < KPROC) g_pidx[b * KPROC + tid] = si[tid];
}

// ---------------- K4b: Wsel gather ------------------------------------------------
__global__ void k_gather_wsel() {
    int b = blockIdx.y, k = blockIdx.x, j = threadIdx.x;
    int col = g_pidx[b * KPROC + j];
    g_Wsel[((size_t)b * KIN + k) * KPROC + j] =
        g_Wg[((size_t)b * KIN + k) * NPROC + col];
}

// ---------------- K5: acts_sel = gelu(X @ Wsel)  [2048,128]x[128,256], fp32 --------
__global__ __launch_bounds__(256) void k_actsel(const float* __restrict__ X) {
    __shared__ float As[16][128];
    __shared__ float Bs[16][128];
    int b = blockIdx.z;
    int m0 = blockIdx.x * 128;
    int n0 = blockIdx.y * 128;
    int tid = threadIdx.x;
    int tx = tid & 15, ty = tid >> 4;
    const float* A = X + (size_t)b * SS * KIN;
    const float* Bm = g_Wsel + (size_t)b * KIN * KPROC;
    float acc[8][8];
    #pragma unroll
    for (int i = 0; i < 8; i++)
        #pragma unroll
        for (int j = 0; j < 8; j++) acc[i][j] = 0.f;

    for (int kc = 0; kc < KIN; kc += 16) {
        #pragma unroll
        for (int it = 0; it < 2; it++) {
            int idx = tid + it * 256;
            int row = idx >> 2, c4 = idx & 3;
            float4 v = *(const float4*)&A[(m0 + row) * KIN + kc + c4 * 4];
            As[c4 * 4 + 0][row] = v.x; As[c4 * 4 + 1][row] = v.y;
            As[c4 * 4 + 2][row] = v.z; As[c4 * 4 + 3][row] = v.w;
        }
        #pragma unroll
        for (int it = 0; it < 2; it++) {
            int idx = tid + it * 256;
            int row = idx >> 5, c4 = idx & 31;
            *(float4*)&Bs[row][c4 * 4] =
                *(const float4*)&Bm[(kc + row) * KPROC + n0 + c4 * 4];
        }
        __syncthreads();
        #pragma unroll
        for (int kk = 0; kk < 16; kk++) {
            float a[8], bv[8];
            #pragma unroll
            for (int i = 0; i < 8; i++) a[i] = As[kk][ty * 8 + i];
            #pragma unroll
            for (int j = 0; j < 8; j++) bv[j] = Bs[kk][tx * 8 + j];
            #pragma unroll
            for (int i = 0; i < 8; i++)
                #pragma unroll
                for (int j = 0; j < 8; j++) acc[i][j] += a[i] * bv[j];
        }
        __syncthreads();
    }
    #pragma unroll
    for (int i = 0; i < 8; i++) {
        int m = m0 + ty * 8 + i;
        float4 v0 = make_float4(gelu_exact(acc[i][0]), gelu_exact(acc[i][1]),
                                gelu_exact(acc[i][2]), gelu_exact(acc[i][3]));
        float4 v1 = make_float4(gelu_exact(acc[i][4]), gelu_exact(acc[i][5]),
                                gelu_exact(acc[i][6]), gelu_exact(acc[i][7]));
        float* dst = &g_asel[((size_t)b * SS + m) * KPROC + n0 + tx * 8];
        *(float4*)dst = v0;
        *(float4*)(dst + 4) = v1;
    }
}

// ---------------- K6: out = acts_sel @ gather(P)  — TF32 tensor cores --------------
// grid (16, 8, 8), 256 threads = 8 warps in 2(M)x4(N); warp tile 64x32.
// wmma m16n16k8 tf32; fp32 accumulate. Only output values affected (~1e-4 rel).
__global__ __launch_bounds__(256) void k_out_tc(const float* __restrict__ P,
                                                float* __restrict__ out) {
    __shared__ float As[128][24];    // [m][k] row-major, ldm 24 (pad: 16-byte mult)
    __shared__ float Bs[16][136];    // [k][n] row-major, ldm 136
    int b = blockIdx.z;
    int m0 = blockIdx.x * 128;
    int n0 = blockIdx.y * 128;
    int tid = threadIdx.x;
    int wid = tid >> 5;
    int wm = wid & 1;                 // 0..1 -> 64-row slab
    int wn = wid >> 1;                // 0..3 -> 32-col slab
    const float* A = g_asel + (size_t)b * SS * KPROC;   // [2048][256]
    const int* pidx = g_pidx + b * KPROC;

    wmma::fragment<wmma::accumulator, 16, 16, 8, float> acc[4][2];
    #pragma unroll
    for (int i = 0; i < 4; i++)
        #pragma unroll
        for (int j = 0; j < 2; j++) wmma::fill_fragment(acc[i][j], 0.0f);

    for (int kc = 0; kc < KPROC; kc += 16) {
        // A tile: 128 rows x 16 k  (512 float4, 2 per thread)
        #pragma unroll
        for (int it = 0; it < 2; it++) {
            int idx = tid + it * 256;
            int row = idx >> 2, c4 = (idx & 3) * 4;
            *(float4*)&As[row][c4] =
                *(const float4*)&A[(m0 + row) * KPROC + kc + c4];
        }
        // B tile: 16 k rows x 128 n, rows gathered from P (512 float4, 2 per thread)
        #pragma unroll
        for (int it = 0; it < 2; it++) {
            int idx = tid + it * 256;
            int row = idx >> 5, c4 = (idx & 31) * 4;
            int pr = pidx[kc + row];
            *(float4*)&Bs[row][c4] =
                *(const float4*)&P[(size_t)pr * DM + n0 + c4];
        }
        __syncthreads();
        #pragma unroll
        for (int ks = 0; ks < 2; ks++) {
            wmma::fragment<wmma::matrix_a, 16, 16, 8, wmma::precision::tf32,
                           wmma::row_major> af[4];
            wmma::fragment<wmma::matrix_b, 16, 16, 8, wmma::precision::tf32,
                           wmma::row_major> bf[2];
            #pragma unroll
            for (int i = 0; i < 4; i++) {
                wmma::load_matrix_sync(af[i], &As[wm * 64 + i * 16][ks * 8], 24);
                #pragma unroll
                for (int t = 0; t < af[i].num_elements; t++)
                    af[i].x[t] = wmma::__float_to_tf32(af[i].x[t]);
            }
            #pragma unroll
            for (int j = 0; j < 2; j++) {
                wmma::load_matrix_sync(bf[j], &Bs[ks * 8][wn * 32 + j * 16], 136);
                #pragma unroll
                for (int t = 0; t < bf[j].num_elements; t++)
                    bf[j].x[t] = wmma::__float_to_tf32(bf[j].x[t]);
            }
            #pragma unroll
            for (int i = 0; i < 4; i++)
                #pragma unroll
                for (int j = 0; j < 2; j++)
                    wmma::mma_sync(acc[i][j], af[i], bf[j], acc[i][j]);
        }
        __syncthreads();
    }
    #pragma unroll
    for (int i = 0; i < 4; i++)
        #pragma unroll
        for (int j = 0; j < 2; j++) {
            float* dst = out + ((size_t)(b * SS + m0 + wm * 64 + i * 16)) * DM
                             + n0 + wn * 32 + j * 16;
            wmma::store_matrix_sync(dst, acc[i][j], DM, wmma::mem_row_major);
        }
}

// ---------------- launch -----------------------------------------------------------
extern "C" void kernel_launch(void* const* d_in, const int* in_sizes, int n_in,
                              void* d_out, int out_size) {
    const float* X    = (const float*)d_in[0];   // [8,2048,128]
    const float* PW   = (const float*)d_in[1];   // [1024,256]
    const float* PO   = (const float*)d_in[2];   // [1024,1024]
    const int*   IIDX = (const int*)d_in[3];     // [8,128]

    k_transpose<<<dim3(NIN / 32, NPROC / 32), dim3(32, 8)>>>(PW);
    k_gather_wg<<<BB * KIN, 256>>>(IIDX);
    k_scores<<<dim3(16, 8, BB), 256>>>(X);
    k_topk<<<BB, 512>>>();
    k_gather_wsel<<<dim3(KIN, BB), 256>>>();
    k_actsel<<<dim3(16, 2, BB), 256>>>(X);
    k_out_tc<<<dim3(16, 8, BB), 256>>>(PO, (float*)d_out);
}

// round 6
// speedup vs baseline: 1.5222x; 1.0904x over previous
#include <cuda_runtime.h>
#include <math.h>
#include <mma.h>

using namespace nvcuda;

#define BB 8
#define SS 2048
#define KIN 128
#define NIN 256
#define NPROC 1024
#define KPROC 256
#define DM 1024

// ---------------- scratch (device globals; no allocation allowed) ----------------
__device__ float g_PWT[NIN * NPROC];          // process_weights^T  [256][1024]
__device__ float g_Wg[BB * KIN * NPROC];      // gathered weights   [8][128][1024]
__device__ float g_part[BB * 16 * NPROC];     // partial col sums   [8][16 mtiles][1024]
__device__ int   g_pidx[BB * KPROC];          // selected neurons   [8][256]
__device__ float g_actsT[(size_t)BB * NPROC * SS]; // gelu acts, transposed, tf32-rounded [8][1024][2048]
__device__ float g_Ptf[NPROC * DM];           // process_outputs, tf32-rounded

__device__ __forceinline__ float gelu_exact(float x) {
    return 0.5f * x * (1.0f + erff(x * 0.70710678118654752f));
}

// ---------------- K0: transpose process_weights [1024][256] -> PWT [256][1024] ----
__global__ void k_transpose(const float* __restrict__ pw) {
    __shared__ float t[32][33];
    int x = blockIdx.x * 32 + threadIdx.x;
    int y = blockIdx.y * 32 + threadIdx.y;
    #pragma unroll
    for (int i = 0; i < 32; i += 8)
        t[threadIdx.y + i][threadIdx.x] = pw[(y + i) * NIN + x];
    __syncthreads();
    int x2 = blockIdx.y * 32 + threadIdx.x;
    int y2 = blockIdx.x * 32 + threadIdx.y;
    #pragma unroll
    for (int i = 0; i < 32; i += 8)
        g_PWT[(y2 + i) * NPROC + x2] = t[threadIdx.x][threadIdx.y + i];
}

// ---------------- K1: gather Wg[b][k][:] = PWT[input_idx[b][k]][:] -----------------
__global__ void k_gather_wg(const int* __restrict__ iidx) {
    int b = blockIdx.x / KIN;
    int k = blockIdx.x % KIN;
    int c = iidx[b * KIN + k];
    const float4* src = (const float4*)&g_PWT[(size_t)c * NPROC];
    float4* dst = (float4*)&g_Wg[((size_t)b * KIN + k) * NPROC];
    dst[threadIdx.x] = src[threadIdx.x];
}

// ---------------- K1b: pre-round process_outputs to tf32 bit patterns --------------
__global__ void k_round_P(const float* __restrict__ P) {
    int idx = blockIdx.x * blockDim.x + threadIdx.x;   // 1M floats / 4
    float4 v = ((const float4*)P)[idx];
    v.x = wmma::__float_to_tf32(v.x); v.y = wmma::__float_to_tf32(v.y);
    v.z = wmma::__float_to_tf32(v.z); v.w = wmma::__float_to_tf32(v.w);
    ((float4*)g_Ptf)[idx] = v;
}

// ---------------- K2: GEMM1 + gelu; stores acts^T (tf32-rounded) + exact col sums --
// grid (16 mtiles, 8 ntiles, 8 batch), 256 threads, 128x128 tile, 8x8 microtile
__global__ __launch_bounds__(256) void k_scores(const float* __restrict__ X) {
    __shared__ float As[16][128];
    __shared__ float Bs[16][128];
    int b = blockIdx.z;
    int m0 = blockIdx.x * 128;
    int n0 = blockIdx.y * 128;
    int tid = threadIdx.x;
    int tx = tid & 15, ty = tid >> 4;
    const float* A = X + (size_t)b * SS * KIN;
    const float* Bm = g_Wg + (size_t)b * KIN * NPROC;
    float acc[8][8];
    #pragma unroll
    for (int i = 0; i < 8; i++)
        #pragma unroll
        for (int j = 0; j < 8; j++) acc[i][j] = 0.f;

    for (int kc = 0; kc < KIN; kc += 16) {
        #pragma unroll
        for (int it = 0; it < 2; it++) {
            int idx = tid + it * 256;
            int row = idx >> 2, c4 = idx & 3;
            float4 v = *(const float4*)&A[(m0 + row) * KIN + kc + c4 * 4];
            As[c4 * 4 + 0][row] = v.x; As[c4 * 4 + 1][row] = v.y;
            As[c4 * 4 + 2][row] = v.z; As[c4 * 4 + 3][row] = v.w;
        }
        #pragma unroll
        for (int it = 0; it < 2; it++) {
            int idx = tid + it * 256;
            int row = idx >> 5, c4 = idx & 31;
            *(float4*)&Bs[row][c4 * 4] =
                *(const float4*)&Bm[(kc + row) * NPROC + n0 + c4 * 4];
        }
        __syncthreads();
        #pragma unroll
        for (int kk = 0; kk < 16; kk++) {
            float a[8], bv[8];
            #pragma unroll
            for (int i = 0; i < 8; i++) a[i] = As[kk][ty * 8 + i];
            #pragma unroll
            for (int j = 0; j < 8; j++) bv[j] = Bs[kk][tx * 8 + j];
            #pragma unroll
            for (int i = 0; i < 8; i++)
                #pragma unroll
                for (int j = 0; j < 8; j++) acc[i][j] += a[i] * bv[j];
        }
        __syncthreads();
    }
    // per-column: exact gelu -> exact cs sums (identical order to prior rounds),
    // and tf32-rounded acts stored transposed for K6's A-gather.
    float cs[8];
    #pragma unroll
    for (int j = 0; j < 8; j++) {
        float gv[8];
        float s = 0.f;
        #pragma unroll
        for (int i = 0; i < 8; i++) { gv[i] = gelu_exact(acc[i][j]); s += gv[i]; }
        cs[j] = s;
        int n = n0 + tx * 8 + j;
        float* dst = &g_actsT[((size_t)b * NPROC + n) * SS + m0 + ty * 8];
        *(float4*)dst = make_float4(
            wmma::__float_to_tf32(gv[0]), wmma::__float_to_tf32(gv[1]),
            wmma::__float_to_tf32(gv[2]), wmma::__float_to_tf32(gv[3]));
        *(float4*)(dst + 4) = make_float4(
            wmma::__float_to_tf32(gv[4]), wmma::__float_to_tf32(gv[5]),
            wmma::__float_to_tf32(gv[6]), wmma::__float_to_tf32(gv[7]));
    }
    __syncthreads();
    #pragma unroll
    for (int j = 0; j < 8; j++) As[ty][tx * 8 + j] = cs[j];
    __syncthreads();
    if (tid < 128) {
        float s = 0.f;
        #pragma unroll
        for (int r = 0; r < 16; r++) s += As[r][tid];
        g_part[((size_t)b * 16 + blockIdx.x) * NPROC + n0 + tid] = s;
    }
}

// ---------------- K4: per-batch reduce + bitonic top-256 of 1024 -------------------
__global__ __launch_bounds__(512) void k_topk() {
    __shared__ float sv[NPROC];
    __shared__ int   si[NPROC];
    int b = blockIdx.x;
    int tid = threadIdx.x;
    for (int t = tid; t < NPROC; t += 512) {
        float s = 0.f;
        #pragma unroll
        for (int r = 0; r < 16; r++) s += g_part[((size_t)b * 16 + r) * NPROC + t];
        sv[t] = s; si[t] = t;
    }
    __syncthreads();
    for (int k = 2; k <= NPROC; k <<= 1) {
        for (int j = k >> 1; j > 0; j >>= 1) {
            int i = ((tid & ~(j - 1)) << 1) | (tid & (j - 1));
            int ixj = i | j;
            bool desc = ((i & k) == 0);
            float v1 = sv[i], v2 = sv[ixj];
            if ((v1 < v2) == desc) {
                sv[i] = v2; sv[ixj] = v1;
                int tmp = si[i]; si[i] = si[ixj]; si[ixj] = tmp;
            }
            __syncthreads();
        }
    }
    if (tid < KPROC) g_pidx[b * KPROC + tid] = si[tid];
}

// ---------------- K6: out = actsT_sel^T @ Ptf_sel — TF32 TC, no conversions --------
// grid (16, 8, 8), 256 threads = 8 warps 2(M)x4(N); warp tile 64x32; K-tile 32.
// A-tile: 32 selected-neuron rows of g_actsT (contiguous m) -> matrix_a col_major.
// B-tile: same 32 neuron rows of g_Ptf (contiguous n)       -> matrix_b row_major.
__global__ __launch_bounds__(256) void k_out_tc(float* __restrict__ out) {
    __shared__ float As[32][136];
    __shared__ float Bs[32][136];
    int b = blockIdx.z;
    int m0 = blockIdx.x * 128;
    int n0 = blockIdx.y * 128;
    int tid = threadIdx.x;
    int wid = tid >> 5;
    int wm = wid & 1;
    int wn = wid >> 1;
    const float* AT = g_actsT + (size_t)b * NPROC * SS;
    const int* pidx = g_pidx + b * KPROC;

    wmma::fragment<wmma::accumulator, 16, 16, 8, float> acc[4][2];
    #pragma unroll
    for (int i = 0; i < 4; i++)
        #pragma unroll
        for (int j = 0; j < 2; j++) wmma::fill_fragment(acc[i][j], 0.0f);

    for (int kc = 0; kc < KPROC; kc += 32) {
        #pragma unroll
        for (int it = 0; it < 4; it++) {
            int idx = tid + it * 256;
            int row = idx >> 5, c4 = (idx & 31) * 4;
            int nr = pidx[kc + row];
            *(float4*)&As[row][c4] = *(const float4*)&AT[(size_t)nr * SS + m0 + c4];
        }
        #pragma unroll
        for (int it = 0; it < 4; it++) {
            int idx = tid + it * 256;
            int row = idx >> 5, c4 = (idx & 31) * 4;
            int nr = pidx[kc + row];
            *(float4*)&Bs[row][c4] = *(const float4*)&g_Ptf[(size_t)nr * DM + n0 + c4];
        }
        __syncthreads();
        #pragma unroll
        for (int ks = 0; ks < 4; ks++) {
            wmma::fragment<wmma::matrix_a, 16, 16, 8, wmma::precision::tf32,
                           wmma::col_major> af[4];
            wmma::fragment<wmma::matrix_b, 16, 16, 8, wmma::precision::tf32,
                           wmma::row_major> bf[2];
            #pragma unroll
            for (int i = 0; i < 4; i++)
                wmma::load_matrix_sync(af[i], &As[ks * 8][wm * 64 + i * 16], 136);
            #pragma unroll
            for (int j = 0; j < 2; j++)
                wmma::load_matrix_sync(bf[j], &Bs[ks * 8][wn * 32 + j * 16], 136);
            #pragma unroll
            for (int i = 0; i < 4; i++)
                #pragma unroll
                for (int j = 0; j < 2; j++)
                    wmma::mma_sync(acc[i][j], af[i], bf[j], acc[i][j]);
        }
        __syncthreads();
    }
    #pragma unroll
    for (int i = 0; i < 4; i++)
        #pragma unroll
        for (int j = 0; j < 2; j++) {
            float* dst = out + ((size_t)(b * SS + m0 + wm * 64 + i * 16)) * DM
                             + n0 + wn * 32 + j * 16;
            wmma::store_matrix_sync(dst, acc[i][j], DM, wmma::mem_row_major);
        }
}

// ---------------- launch -----------------------------------------------------------
extern "C" void kernel_launch(void* const* d_in, const int* in_sizes, int n_in,
                              void* d_out, int out_size) {
    const float* X    = (const float*)d_in[0];   // [8,2048,128]
    const float* PW   = (const float*)d_in[1];   // [1024,256]
    const float* PO   = (const float*)d_in[2];   // [1024,1024]
    const int*   IIDX = (const int*)d_in[3];     // [8,128]

    k_transpose<<<dim3(NIN / 32, NPROC / 32), dim3(32, 8)>>>(PW);
    k_gather_wg<<<BB * KIN, 256>>>(IIDX);
    k_round_P<<<(NPROC * DM / 4) / 256, 256>>>(PO);
    k_scores<<<dim3(16, 8, BB), 256>>>(X);
    k_topk<<<BB, 512>>>();
    k_out_tc<<<dim3(16, 8, BB), 256>>>((float*)d_out);
}

// round 7
// speedup vs baseline: 1.5368x; 1.0095x over previous
#include <cuda_runtime.h>
#include <math.h>
#include <mma.h>

using namespace nvcuda;

#define BB 8
#define SS 2048
#define KIN 128
#define NIN 256
#define NPROC 1024
#define KPROC 256
#define DM 1024

// ---------------- scratch (device globals; no allocation allowed) ----------------
__device__ float g_PWT[NIN * NPROC];          // process_weights^T  [256][1024]
__device__ float g_Wg[BB * KIN * NPROC];      // gathered weights   [8][128][1024]
__device__ float g_part[BB * 16 * NPROC];     // partial col sums   [8][16 mtiles][1024]
__device__ int   g_pidx[BB * KPROC];          // selected neurons   [8][256]
__device__ float g_actsT[(size_t)BB * NPROC * SS]; // gelu acts, transposed, tf32-rounded
__device__ float g_Ptf[NPROC * DM];           // process_outputs, tf32-rounded

__device__ __forceinline__ float gelu_exact(float x) {
    return 0.5f * x * (1.0f + erff(x * 0.70710678118654752f));
}

// ---------------- K0: transpose process_weights [1024][256] -> PWT [256][1024] ----
__global__ void k_transpose(const float* __restrict__ pw) {
    __shared__ float t[32][33];
    int x = blockIdx.x * 32 + threadIdx.x;
    int y = blockIdx.y * 32 + threadIdx.y;
    #pragma unroll
    for (int i = 0; i < 32; i += 8)
        t[threadIdx.y + i][threadIdx.x] = pw[(y + i) * NIN + x];
    __syncthreads();
    int x2 = blockIdx.y * 32 + threadIdx.x;
    int y2 = blockIdx.x * 32 + threadIdx.y;
    #pragma unroll
    for (int i = 0; i < 32; i += 8)
        g_PWT[(y2 + i) * NPROC + x2] = t[threadIdx.x][threadIdx.y + i];
}

// ---------------- K1: gather Wg[b][k][:] = PWT[input_idx[b][k]][:] -----------------
__global__ void k_gather_wg(const int* __restrict__ iidx) {
    int b = blockIdx.x / KIN;
    int k = blockIdx.x % KIN;
    int c = iidx[b * KIN + k];
    const float4* src = (const float4*)&g_PWT[(size_t)c * NPROC];
    float4* dst = (float4*)&g_Wg[((size_t)b * KIN + k) * NPROC];
    dst[threadIdx.x] = src[threadIdx.x];
}

// ---------------- K1b: pre-round process_outputs to tf32 bit patterns --------------
__global__ void k_round_P(const float* __restrict__ P) {
    int idx = blockIdx.x * blockDim.x + threadIdx.x;
    float4 v = ((const float4*)P)[idx];
    v.x = wmma::__float_to_tf32(v.x); v.y = wmma::__float_to_tf32(v.y);
    v.z = wmma::__float_to_tf32(v.z); v.w = wmma::__float_to_tf32(v.w);
    ((float4*)g_Ptf)[idx] = v;
}

// ---------------- K2: GEMM1 + gelu; stores acts^T (tf32-rounded) + exact col sums --
// 128x128 tile, 8x8 microtile; B microtile split into cols {tx*4..+3} and
// {64+tx*4..+3} -> conflict-free LDS.128 phases (bank starts 0,4,...,28).
__global__ __launch_bounds__(256) void k_scores(const float* __restrict__ X) {
    __shared__ float As[16][128];
    __shared__ float Bs[16][128];
    int b = blockIdx.z;
    int m0 = blockIdx.x * 128;
    int n0 = blockIdx.y * 128;
    int tid = threadIdx.x;
    int tx = tid & 15, ty = tid >> 4;
    const float* A = X + (size_t)b * SS * KIN;
    const float* Bm = g_Wg + (size_t)b * KIN * NPROC;
    float acc[8][8];
    #pragma unroll
    for (int i = 0; i < 8; i++)
        #pragma unroll
        for (int j = 0; j < 8; j++) acc[i][j] = 0.f;

    for (int kc = 0; kc < KIN; kc += 16) {
        #pragma unroll
        for (int it = 0; it < 2; it++) {
            int idx = tid + it * 256;
            int row = idx >> 2, c4 = idx & 3;
            float4 v = *(const float4*)&A[(m0 + row) * KIN + kc + c4 * 4];
            As[c4 * 4 + 0][row] = v.x; As[c4 * 4 + 1][row] = v.y;
            As[c4 * 4 + 2][row] = v.z; As[c4 * 4 + 3][row] = v.w;
        }
        #pragma unroll
        for (int it = 0; it < 2; it++) {
            int idx = tid + it * 256;
            int row = idx >> 5, c4 = idx & 31;
            *(float4*)&Bs[row][c4 * 4] =
                *(const float4*)&Bm[(kc + row) * NPROC + n0 + c4 * 4];
        }
        __syncthreads();
        #pragma unroll
        for (int kk = 0; kk < 16; kk++) {
            float a[8], bv[8];
            #pragma unroll
            for (int i = 0; i < 8; i++) a[i] = As[kk][ty * 8 + i];
            *(float4*)&bv[0] = *(const float4*)&Bs[kk][tx * 4];
            *(float4*)&bv[4] = *(const float4*)&Bs[kk][64 + tx * 4];
            #pragma unroll
            for (int i = 0; i < 8; i++)
                #pragma unroll
                for (int j = 0; j < 8; j++) acc[i][j] += a[i] * bv[j];
        }
        __syncthreads();
    }
    // column mapping: j<4 -> n0+tx*4+j ; j>=4 -> n0+64+tx*4+(j-4)
    float cs[8];
    #pragma unroll
    for (int j = 0; j < 8; j++) {
        float gv[8];
        float s = 0.f;
        #pragma unroll
        for (int i = 0; i < 8; i++) { gv[i] = gelu_exact(acc[i][j]); s += gv[i]; }
        cs[j] = s;
        int ncol = (j < 4) ? (tx * 4 + j) : (64 + tx * 4 + (j - 4));
        int n = n0 + ncol;
        float* dst = &g_actsT[((size_t)b * NPROC + n) * SS + m0 + ty * 8];
        *(float4*)dst = make_float4(
            wmma::__float_to_tf32(gv[0]), wmma::__float_to_tf32(gv[1]),
            wmma::__float_to_tf32(gv[2]), wmma::__float_to_tf32(gv[3]));
        *(float4*)(dst + 4) = make_float4(
            wmma::__float_to_tf32(gv[4]), wmma::__float_to_tf32(gv[5]),
            wmma::__float_to_tf32(gv[6]), wmma::__float_to_tf32(gv[7]));
    }
    __syncthreads();
    #pragma unroll
    for (int j = 0; j < 8; j++) {
        int ncol = (j < 4) ? (tx * 4 + j) : (64 + tx * 4 + (j - 4));
        As[ty][ncol] = cs[j];
    }
    __syncthreads();
    if (tid < 128) {
        float s = 0.f;
        #pragma unroll
        for (int r = 0; r < 16; r++) s += As[r][tid];
        g_part[((size_t)b * 16 + blockIdx.x) * NPROC + n0 + tid] = s;
    }
}

// ---------------- K4: per-batch reduce + bitonic top-256 of 1024 -------------------
__global__ __launch_bounds__(512) void k_topk() {
    __shared__ float sv[NPROC];
    __shared__ int   si[NPROC];
    int b = blockIdx.x;
    int tid = threadIdx.x;
    for (int t = tid; t < NPROC; t += 512) {
        float s = 0.f;
        #pragma unroll
        for (int r = 0; r < 16; r++) s += g_part[((size_t)b * 16 + r) * NPROC + t];
        sv[t] = s; si[t] = t;
    }
    __syncthreads();
    for (int k = 2; k <= NPROC; k <<= 1) {
        for (int j = k >> 1; j > 0; j >>= 1) {
            int i = ((tid & ~(j - 1)) << 1) | (tid & (j - 1));
            int ixj = i | j;
            bool desc = ((i & k) == 0);
            float v1 = sv[i], v2 = sv[ixj];
            if ((v1 < v2) == desc) {
                sv[i] = v2; sv[ixj] = v1;
                int tmp = si[i]; si[i] = si[ixj]; si[ixj] = tmp;
            }
            __syncthreads();
        }
    }
    if (tid < KPROC) g_pidx[b * KPROC + tid] = si[tid];
}

// ---------------- K6: out = actsT_sel^T @ Ptf_sel — TF32 TC ------------------------
// 128 threads = 4 warps (2x2), warp tile 64x64 (af[4] x bf[4], 16 mma per ks):
// fragment-load:mma ratio 8:16 vs prior 6:8 -> 1.5x less LDS per FLOP.
__global__ __launch_bounds__(128) void k_out_tc(float* __restrict__ out) {
    __shared__ float As[32][136];   // [k][m]
    __shared__ float Bs[32][136];   // [k][n]
    int b = blockIdx.z;
    int m0 = blockIdx.x * 128;
    int n0 = blockIdx.y * 128;
    int tid = threadIdx.x;
    int wid = tid >> 5;
    int wm = wid & 1;                 // 64-row slab
    int wn = wid >> 1;                // 64-col slab
    const float* AT = g_actsT + (size_t)b * NPROC * SS;
    const int* pidx = g_pidx + b * KPROC;

    wmma::fragment<wmma::accumulator, 16, 16, 8, float> acc[4][4];
    #pragma unroll
    for (int i = 0; i < 4; i++)
        #pragma unroll
        for (int j = 0; j < 4; j++) wmma::fill_fragment(acc[i][j], 0.0f);

    for (int kc = 0; kc < KPROC; kc += 32) {
        #pragma unroll
        for (int it = 0; it < 8; it++) {
            int idx = tid + it * 128;
            int row = idx >> 5, c4 = (idx & 31) * 4;
            int nr = pidx[kc + row];
            *(float4*)&As[row][c4] = *(const float4*)&AT[(size_t)nr * SS + m0 + c4];
        }
        #pragma unroll
        for (int it = 0; it < 8; it++) {
            int idx = tid + it * 128;
            int row = idx >> 5, c4 = (idx & 31) * 4;
            int nr = pidx[kc + row];
            *(float4*)&Bs[row][c4] = *(const float4*)&g_Ptf[(size_t)nr * DM + n0 + c4];
        }
        __syncthreads();
        #pragma unroll
        for (int ks = 0; ks < 4; ks++) {
            wmma::fragment<wmma::matrix_a, 16, 16, 8, wmma::precision::tf32,
                           wmma::col_major> af[4];
            wmma::fragment<wmma::matrix_b, 16, 16, 8, wmma::precision::tf32,
                           wmma::row_major> bf[4];
            #pragma unroll
            for (int i = 0; i < 4; i++)
                wmma::load_matrix_sync(af[i], &As[ks * 8][wm * 64 + i * 16], 136);
            #pragma unroll
            for (int j = 0; j < 4; j++)
                wmma::load_matrix_sync(bf[j], &Bs[ks * 8][wn * 64 + j * 16], 136);
            #pragma unroll
            for (int i = 0; i < 4; i++)
                #pragma unroll
                for (int j = 0; j < 4; j++)
                    wmma::mma_sync(acc[i][j], af[i], bf[j], acc[i][j]);
        }
        __syncthreads();
    }
    #pragma unroll
    for (int i = 0; i < 4; i++)
        #pragma unroll
        for (int j = 0; j < 4; j++) {
            float* dst = out + ((size_t)(b * SS + m0 + wm * 64 + i * 16)) * DM
                             + n0 + wn * 64 + j * 16;
            wmma::store_matrix_sync(dst, acc[i][j], DM, wmma::mem_row_major);
        }
}

// ---------------- launch -----------------------------------------------------------
extern "C" void kernel_launch(void* const* d_in, const int* in_sizes, int n_in,
                              void* d_out, int out_size) {
    const float* X    = (const float*)d_in[0];   // [8,2048,128]
    const float* PW   = (const float*)d_in[1];   // [1024,256]
    const float* PO   = (const float*)d_in[2];   // [1024,1024]
    const int*   IIDX = (const int*)d_in[3];     // [8,128]

    k_transpose<<<dim3(NIN / 32, NPROC / 32), dim3(32, 8)>>>(PW);
    k_gather_wg<<<BB * KIN, 256>>>(IIDX);
    k_round_P<<<(NPROC * DM / 4) / 256, 256>>>(PO);
    k_scores<<<dim3(16, 8, BB), 256>>>(X);
    k_topk<<<BB, 512>>>();
    k_out_tc<<<dim3(16, 8, BB), 128>>>((float*)d_out);
}

// round 8
// speedup vs baseline: 1.6185x; 1.0532x over previous
#include <cuda_runtime.h>
#include <math.h>
#include <mma.h>

using namespace nvcuda;

#define BB 8
#define SS 2048
#define KIN 128
#define NIN 256
#define NPROC 1024
#define KPROC 256
#define DM 1024

// ---------------- scratch (device globals; no allocation allowed) ----------------
__device__ float g_PWT[NIN * NPROC];
__device__ float g_Wg[BB * KIN * NPROC];
__device__ float g_part[BB * 16 * NPROC];
__device__ int   g_pidx[BB * KPROC];
__device__ float g_actsT[(size_t)BB * NPROC * SS]; // gelu acts, transposed, tf32-rounded
__device__ float g_Ptf[NPROC * DM];                // process_outputs, tf32-rounded

__device__ __forceinline__ float gelu_exact(float x) {
    return 0.5f * x * (1.0f + erff(x * 0.70710678118654752f));
}

// ---------------- K0: transpose process_weights [1024][256] -> PWT [256][1024] ----
__global__ void k_transpose(const float* __restrict__ pw) {
    __shared__ float t[32][33];
    int x = blockIdx.x * 32 + threadIdx.x;
    int y = blockIdx.y * 32 + threadIdx.y;
    #pragma unroll
    for (int i = 0; i < 32; i += 8)
        t[threadIdx.y + i][threadIdx.x] = pw[(y + i) * NIN + x];
    __syncthreads();
    int x2 = blockIdx.y * 32 + threadIdx.x;
    int y2 = blockIdx.x * 32 + threadIdx.y;
    #pragma unroll
    for (int i = 0; i < 32; i += 8)
        g_PWT[(y2 + i) * NPROC + x2] = t[threadIdx.x][threadIdx.y + i];
}

// ---------------- K1: gather Wg[b][k][:] = PWT[input_idx[b][k]][:] -----------------
__global__ void k_gather_wg(const int* __restrict__ iidx) {
    int b = blockIdx.x / KIN;
    int k = blockIdx.x % KIN;
    int c = iidx[b * KIN + k];
    const float4* src = (const float4*)&g_PWT[(size_t)c * NPROC];
    float4* dst = (float4*)&g_Wg[((size_t)b * KIN + k) * NPROC];
    dst[threadIdx.x] = src[threadIdx.x];
}

// ---------------- K1b: pre-round process_outputs to tf32 bit patterns --------------
__global__ void k_round_P(const float* __restrict__ P) {
    int idx = blockIdx.x * blockDim.x + threadIdx.x;
    float4 v = ((const float4*)P)[idx];
    v.x = wmma::__float_to_tf32(v.x); v.y = wmma::__float_to_tf32(v.y);
    v.z = wmma::__float_to_tf32(v.z); v.w = wmma::__float_to_tf32(v.w);
    ((float4*)g_Ptf)[idx] = v;
}

// ---------------- K2: GEMM1 + gelu; K-tile 32 (half the barriers) ------------------
// 128x128 tile, 8x8 microtile; k order strictly sequential -> scores bit-identical.
__global__ __launch_bounds__(256) void k_scores(const float* __restrict__ X) {
    __shared__ float As[32][128];
    __shared__ float Bs[32][128];
    int b = blockIdx.z;
    int m0 = blockIdx.x * 128;
    int n0 = blockIdx.y * 128;
    int tid = threadIdx.x;
    int tx = tid & 15, ty = tid >> 4;
    const float* A = X + (size_t)b * SS * KIN;
    const float* Bm = g_Wg + (size_t)b * KIN * NPROC;
    float acc[8][8];
    #pragma unroll
    for (int i = 0; i < 8; i++)
        #pragma unroll
        for (int j = 0; j < 8; j++) acc[i][j] = 0.f;

    for (int kc = 0; kc < KIN; kc += 32) {
        // A tile: 128 rows x 32 k -> As[k][m]  (1024 float4, 4 per thread)
        #pragma unroll
        for (int it = 0; it < 4; it++) {
            int idx = tid + it * 256;
            int row = idx >> 3, c4 = (idx & 7) * 4;
            float4 v = *(const float4*)&A[(m0 + row) * KIN + kc + c4];
            As[c4 + 0][row] = v.x; As[c4 + 1][row] = v.y;
            As[c4 + 2][row] = v.z; As[c4 + 3][row] = v.w;
        }
        // B tile: 32 k rows x 128 n (1024 float4, 4 per thread)
        #pragma unroll
        for (int it = 0; it < 4; it++) {
            int idx = tid + it * 256;
            int row = idx >> 5, c4 = (idx & 31) * 4;
            *(float4*)&Bs[row][c4] =
                *(const float4*)&Bm[(kc + row) * NPROC + n0 + c4];
        }
        __syncthreads();
        #pragma unroll
        for (int kk = 0; kk < 32; kk++) {
            float a[8], bv[8];
            #pragma unroll
            for (int i = 0; i < 8; i++) a[i] = As[kk][ty * 8 + i];
            *(float4*)&bv[0] = *(const float4*)&Bs[kk][tx * 4];
            *(float4*)&bv[4] = *(const float4*)&Bs[kk][64 + tx * 4];
            #pragma unroll
            for (int i = 0; i < 8; i++)
                #pragma unroll
                for (int j = 0; j < 8; j++) acc[i][j] += a[i] * bv[j];
        }
        __syncthreads();
    }
    // column mapping: j<4 -> n0+tx*4+j ; j>=4 -> n0+64+tx*4+(j-4)
    float cs[8];
    #pragma unroll
    for (int j = 0; j < 8; j++) {
        float gv[8];
        float s = 0.f;
        #pragma unroll
        for (int i = 0; i < 8; i++) { gv[i] = gelu_exact(acc[i][j]); s += gv[i]; }
        cs[j] = s;
        int ncol = (j < 4) ? (tx * 4 + j) : (64 + tx * 4 + (j - 4));
        int n = n0 + ncol;
        float* dst = &g_actsT[((size_t)b * NPROC + n) * SS + m0 + ty * 8];
        *(float4*)dst = make_float4(
            wmma::__float_to_tf32(gv[0]), wmma::__float_to_tf32(gv[1]),
            wmma::__float_to_tf32(gv[2]), wmma::__float_to_tf32(gv[3]));
        *(float4*)(dst + 4) = make_float4(
            wmma::__float_to_tf32(gv[4]), wmma::__float_to_tf32(gv[5]),
            wmma::__float_to_tf32(gv[6]), wmma::__float_to_tf32(gv[7]));
    }
    __syncthreads();
    #pragma unroll
    for (int j = 0; j < 8; j++) {
        int ncol = (j < 4) ? (tx * 4 + j) : (64 + tx * 4 + (j - 4));
        As[ty][ncol] = cs[j];
    }
    __syncthreads();
    if (tid < 128) {
        float s = 0.f;
        #pragma unroll
        for (int r = 0; r < 16; r++) s += As[r][tid];
        g_part[((size_t)b * 16 + blockIdx.x) * NPROC + n0 + tid] = s;
    }
}

// ---------------- K4: per-batch reduce + bitonic top-256 of 1024 -------------------
__global__ __launch_bounds__(512) void k_topk() {
    __shared__ float sv[NPROC];
    __shared__ int   si[NPROC];
    int b = blockIdx.x;
    int tid = threadIdx.x;
    for (int t = tid; t < NPROC; t += 512) {
        float s = 0.f;
        #pragma unroll
        for (int r = 0; r < 16; r++) s += g_part[((size_t)b * 16 + r) * NPROC + t];
        sv[t] = s; si[t] = t;
    }
    __syncthreads();
    for (int k = 2; k <= NPROC; k <<= 1) {
        for (int j = k >> 1; j > 0; j >>= 1) {
            int i = ((tid & ~(j - 1)) << 1) | (tid & (j - 1));
            int ixj = i | j;
            bool desc = ((i & k) == 0);
            float v1 = sv[i], v2 = sv[ixj];
            if ((v1 < v2) == desc) {
                sv[i] = v2; sv[ixj] = v1;
                int tmp = si[i]; si[i] = si[ixj]; si[ixj] = tmp;
            }
            __syncthreads();
        }
    }
    if (tid < KPROC) g_pidx[b * KPROC + tid] = si[tid];
}

// ---------------- K6: out = actsT_sel^T @ Ptf_sel — TF32 TC + cp.async pipeline ----
// 128 threads = 4 warps (2x2), warp tile 64x64; K-tile 32; 2-stage cp.async
// double buffer in dynamic smem (69632 B) -> gmem latency overlapped with mma.
#define K6_STAGE_F 8704              // floats per stage: As 32*136 + Bs 32*136
__device__ __forceinline__ void k6_issue_stage(float* dsm, int s, int kc,
                                               const float* AT, const int* pidx,
                                               int m0, int n0, int tid) {
    float* As_ = dsm + s * K6_STAGE_F;
    float* Bs_ = As_ + 4352;
    #pragma unroll
    for (int it = 0; it < 8; it++) {
        int idx = tid + it * 128;
        int row = idx >> 5, c4 = (idx & 31) * 4;
        int nr = pidx[kc + row];
        unsigned dst = (unsigned)__cvta_generic_to_shared(&As_[row * 136 + c4]);
        const float* src = &AT[(size_t)nr * SS + m0 + c4];
        asm volatile("cp.async.cg.shared.global [%0], [%1], 16;\n"
                     :: "r"(dst), "l"(src));
    }
    #pragma unroll
    for (int it = 0; it < 8; it++) {
        int idx = tid + it * 128;
        int row = idx >> 5, c4 = (idx & 31) * 4;
        int nr = pidx[kc + row];
        unsigned dst = (unsigned)__cvta_generic_to_shared(&Bs_[row * 136 + c4]);
        const float* src = &g_Ptf[(size_t)nr * DM + n0 + c4];
        asm volatile("cp.async.cg.shared.global [%0], [%1], 16;\n"
                     :: "r"(dst), "l"(src));
    }
    asm volatile("cp.async.commit_group;\n" ::);
}

__global__ __launch_bounds__(128) void k_out_tc(float* __restrict__ out) {
    extern __shared__ float dsm[];
    int b = blockIdx.z;
    int m0 = blockIdx.x * 128;
    int n0 = blockIdx.y * 128;
    int tid = threadIdx.x;
    int wid = tid >> 5;
    int wm = wid & 1;
    int wn = wid >> 1;
    const float* AT = g_actsT + (size_t)b * NPROC * SS;
    const int* pidx = g_pidx + b * KPROC;

    wmma::fragment<wmma::accumulator, 16, 16, 8, float> acc[4][4];
    #pragma unroll
    for (int i = 0; i < 4; i++)
        #pragma unroll
        for (int j = 0; j < 4; j++) wmma::fill_fragment(acc[i][j], 0.0f);

    k6_issue_stage(dsm, 0, 0, AT, pidx, m0, n0, tid);
    k6_issue_stage(dsm, 1, 32, AT, pidx, m0, n0, tid);

    #pragma unroll
    for (int t = 0; t < 8; t++) {
        if (t < 7) asm volatile("cp.async.wait_group 1;\n" ::);
        else       asm volatile("cp.async.wait_group 0;\n" ::);
        __syncthreads();
        int s = t & 1;
        float* As_ = dsm + s * K6_STAGE_F;
        float* Bs_ = As_ + 4352;
        #pragma unroll
        for (int ks = 0; ks < 4; ks++) {
            wmma::fragment<wmma::matrix_a, 16, 16, 8, wmma::precision::tf32,
                           wmma::col_major> af[4];
            wmma::fragment<wmma::matrix_b, 16, 16, 8, wmma::precision::tf32,
                           wmma::row_major> bf[4];
            #pragma unroll
            for (int i = 0; i < 4; i++)
                wmma::load_matrix_sync(af[i], &As_[(ks * 8) * 136 + wm * 64 + i * 16], 136);
            #pragma unroll
            for (int j = 0; j < 4; j++)
                wmma::load_matrix_sync(bf[j], &Bs_[(ks * 8) * 136 + wn * 64 + j * 16], 136);
            #pragma unroll
            for (int i = 0; i < 4; i++)
                #pragma unroll
                for (int j = 0; j < 4; j++)
                    wmma::mma_sync(acc[i][j], af[i], bf[j], acc[i][j]);
        }
        __syncthreads();
        if (t + 2 < 8)
            k6_issue_stage(dsm, s, (t + 2) * 32, AT, pidx, m0, n0, tid);
    }
    #pragma unroll
    for (int i = 0; i < 4; i++)
        #pragma unroll
        for (int j = 0; j < 4; j++) {
            float* dst = out + ((size_t)(b * SS + m0 + wm * 64 + i * 16)) * DM
                             + n0 + wn * 64 + j * 16;
            wmma::store_matrix_sync(dst, acc[i][j], DM, wmma::mem_row_major);
        }
}

// ---------------- launch -----------------------------------------------------------
extern "C" void kernel_launch(void* const* d_in, const int* in_sizes, int n_in,
                              void* d_out, int out_size) {
    const float* X    = (const float*)d_in[0];   // [8,2048,128]
    const float* PW   = (const float*)d_in[1];   // [1024,256]
    const float* PO   = (const float*)d_in[2];   // [1024,1024]
    const int*   IIDX = (const int*)d_in[3];     // [8,128]

    static int smem_set = 0;
    if (!smem_set) {
        cudaFuncSetAttribute(k_out_tc, cudaFuncAttributeMaxDynamicSharedMemorySize,
                             2 * K6_STAGE_F * 4);
        smem_set = 1;
    }

    k_transpose<<<dim3(NIN / 32, NPROC / 32), dim3(32, 8)>>>(PW);
    k_gather_wg<<<BB * KIN, 256>>>(IIDX);
    k_round_P<<<(NPROC * DM / 4) / 256, 256>>>(PO);
    k_scores<<<dim3(16, 8, BB), 256>>>(X);
    k_topk<<<BB, 512>>>();
    k_out_tc<<<dim3(16, 8, BB), 128, 2 * K6_STAGE_F * 4>>>((float*)d_out);
}